// round 1
// baseline (speedup 1.0000x reference)
#include <cuda_runtime.h>
#include <cstdint>
#include <cstddef>

#define BB   16
#define PP   22536
#define NOBJ 32
#define NCLS 80

// ---------------- persistent device scratch (no allocs allowed) ---------------
__device__ unsigned long long g_obj_key[BB * NOBJ];   // per-(img,obj): (iou_bits<<32)|~prior
__device__ float g_best_ov[BB * PP];                  // per-prior best overlap
__device__ int   g_best_obj[BB * PP];                 // per-prior best object idx
__device__ float g_conf_part[4096];
__device__ float g_loc_part[4096];
__device__ int   g_npos_part[4096];

// ---------------- init: zero the per-object keys each run ---------------------
__global__ void k_init() {
    int i = blockIdx.x * blockDim.x + threadIdx.x;
    if (i < BB * NOBJ) g_obj_key[i] = 0ull;
}

// ---------------- matching: IoU, per-prior argmax, per-object argmax ----------
__global__ void k_match(const float* __restrict__ boxes,
                        const float* __restrict__ priors) {
    int b   = blockIdx.y;
    int pr0 = blockIdx.x * blockDim.x + threadIdx.x;
    int pr  = pr0 < PP ? pr0 : PP - 1;
    bool live = (pr0 < PP);

    float4 pc = ((const float4*)priors)[pr];
    float hx = 0.5f * pc.z, hy = 0.5f * pc.w;
    float px1 = pc.x - hx, py1 = pc.y - hy;
    float px2 = pc.x + hx, py2 = pc.y + hy;
    float parea = (px2 - px1) * (py2 - py1);

    __shared__ float4 sbox[NOBJ];
    if (threadIdx.x < NOBJ)
        sbox[threadIdx.x] = ((const float4*)boxes)[b * NOBJ + threadIdx.x];
    __syncthreads();

    float best = -1.0f;
    int   besto = 0;
    int   lane = threadIdx.x & 31;

    #pragma unroll 4
    for (int o = 0; o < NOBJ; o++) {
        float4 bx = sbox[o];
        float ltx = fmaxf(px1, bx.x), lty = fmaxf(py1, bx.y);
        float rbx = fminf(px2, bx.z), rby = fminf(py2, bx.w);
        float iw = fmaxf(rbx - ltx, 0.0f), ih = fmaxf(rby - lty, 0.0f);
        float inter = iw * ih;
        float ab = (bx.z - bx.x) * (bx.w - bx.y);
        float iou = __fdividef(inter, parea + ab - inter);

        if (live && iou > best) { best = iou; besto = o; }   // strict > => first-max (argmax)

        // per-object max over priors: pack (iou_bits, ~prior); ties -> smaller prior
        unsigned long long key = 0ull;
        if (live)
            key = (((unsigned long long)__float_as_uint(iou)) << 32)
                | (unsigned long long)(0xFFFFFFFFu - (unsigned)pr);
        #pragma unroll
        for (int s = 16; s > 0; s >>= 1) {
            unsigned long long other = __shfl_xor_sync(0xFFFFFFFFu, key, s);
            if (other > key) key = other;
        }
        if (lane == 0 && key != 0ull)
            atomicMax(&g_obj_key[b * NOBJ + o], key);
    }

    if (live) {
        g_best_ov[b * PP + pr]  = best;
        g_best_obj[b * PP + pr] = besto;
    }
}

// ------------- force best prior per object (sequential, replicates jax scatter) ----
__global__ void k_force() {
    int b = threadIdx.x;
    if (b >= BB) return;
    int cnt = 0;
    for (int j = 0; j < NOBJ; j++) {
        unsigned long long key = g_obj_key[b * NOBJ + j];
        float ov = __uint_as_float((unsigned)(key >> 32));
        if (ov > 0.0f) {                     // valid object
            int pr = (int)(0xFFFFFFFFu - (unsigned)(key & 0xFFFFFFFFull));
            g_best_ov[b * PP + pr]  = 1.0f;
            g_best_obj[b * PP + pr] = cnt;   // filtered-list index (cumsum(valid)-1)
            cnt++;
        }
    }
}

// ---------------- focal + smooth-L1 loss ---------------------------------------
// g(x) = sigmoid(x)^2 * softplus(x), computed stably:
//   a = exp(-|x|); u = 1+a; s = (x>=0 ? 1/u : a/u); sp = max(x,0) + log(u)
__device__ __forceinline__ float gfun(float x) {
    float ax = fabsf(x);
    float a  = __expf(-ax);        // MUFU.EX2
    float u  = 1.0f + a;
    float L  = __logf(u);          // MUFU.LG2 : log1p(a)
    float r;
    asm("rcp.approx.f32 %0, %1;" : "=f"(r) : "f"(u));   // MUFU.RCP
    float s  = (x >= 0.0f) ? r : a * r;
    float sp = fmaxf(x, 0.0f) + L;
    return s * s * sp;
}

__device__ __forceinline__ float sl1(float d) {
    float ad = fabsf(d);
    return (ad < 1.0f) ? 0.5f * d * d : ad - 0.5f;
}

__global__ void __launch_bounds__(256)
k_loss(const float* __restrict__ plocs, const float* __restrict__ pscores,
       const float* __restrict__ boxes, const int* __restrict__ labels,
       const float* __restrict__ priors) {
    int idx = blockIdx.x * blockDim.x + threadIdx.x;
    float conf = 0.0f, loc = 0.0f;
    int np = 0;

    if (idx < BB * PP) {
        int b  = idx / PP;
        int pr = idx - b * PP;
        float ov = g_best_ov[idx];
        int  obj = g_best_obj[idx];
        int t = (ov < 0.4f) ? 0 : ((ov < 0.5f) ? -1 : labels[b * NOBJ + obj]);

        if (t >= 0) {   // t == -1 (ignore) contributes nothing at all
            const float4* srow = (const float4*)(pscores + (size_t)idx * NCLS);
            #pragma unroll 5
            for (int i = 0; i < NCLS / 4; i++) {
                float4 v = srow[i];
                conf += gfun(v.x);
                conf += gfun(v.y);
                conf += gfun(v.z);
                conf += gfun(v.w);
            }
            conf *= 0.75f;            // all-negative baseline

            if (t > 0) {              // positive prior: fix up its one positive column
                np = 1;
                float xk = pscores[(size_t)idx * NCLS + (t - 1)];
                conf += 0.25f * gfun(-xk) - 0.75f * gfun(xk);

                float4 bx  = ((const float4*)boxes)[b * NOBJ + obj];
                float4 pcv = ((const float4*)priors)[pr];
                float cx = 0.5f * (bx.x + bx.z), cy = 0.5f * (bx.y + bx.w);
                float w  = bx.z - bx.x,          h  = bx.w - bx.y;
                float g0 = __fdividef(cx - pcv.x, 0.1f * pcv.z);
                float g1 = __fdividef(cy - pcv.y, 0.1f * pcv.w);
                float g2 = 5.0f * __logf(__fdividef(w, pcv.z));
                float g3 = 5.0f * __logf(__fdividef(h, pcv.w));
                float4 pl = ((const float4*)plocs)[idx];
                loc = sl1(pl.x - g0) + sl1(pl.y - g1) + sl1(pl.z - g2) + sl1(pl.w - g3);
            }
        }
    }

    // deterministic block reduction
    __shared__ float sc[256];
    __shared__ float sl[256];
    __shared__ int   sn[256];
    int tid = threadIdx.x;
    sc[tid] = conf; sl[tid] = loc; sn[tid] = np;
    __syncthreads();
    #pragma unroll
    for (int s = 128; s > 0; s >>= 1) {
        if (tid < s) {
            sc[tid] += sc[tid + s];
            sl[tid] += sl[tid + s];
            sn[tid] += sn[tid + s];
        }
        __syncthreads();
    }
    if (tid == 0) {
        g_conf_part[blockIdx.x] = sc[0];
        g_loc_part[blockIdx.x]  = sl[0];
        g_npos_part[blockIdx.x] = sn[0];
    }
}

// ---------------- final deterministic reduction --------------------------------
__global__ void k_final(float* __restrict__ out, int nblk) {
    __shared__ double sc[256];
    __shared__ double sl[256];
    __shared__ int    sn[256];
    int tid = threadIdx.x;
    double c = 0.0, l = 0.0;
    int n = 0;
    for (int i = tid; i < nblk; i += 256) {
        c += (double)g_conf_part[i];
        l += (double)g_loc_part[i];
        n += g_npos_part[i];
    }
    sc[tid] = c; sl[tid] = l; sn[tid] = n;
    __syncthreads();
    #pragma unroll
    for (int s = 128; s > 0; s >>= 1) {
        if (tid < s) {
            sc[tid] += sc[tid + s];
            sl[tid] += sl[tid + s];
            sn[tid] += sn[tid + s];
        }
        __syncthreads();
    }
    if (tid == 0) {
        double npos = (double)(sn[0] > 1 ? sn[0] : 1);
        out[0] = (float)(sc[0] / npos + sl[0] / (npos * 4.0));
    }
}

// ---------------- launch ---------------------------------------------------------
extern "C" void kernel_launch(void* const* d_in, const int* in_sizes, int n_in,
                              void* d_out, int out_size) {
    const float* plocs   = (const float*)d_in[0];   // [16,22536,4]
    const float* pscores = (const float*)d_in[1];   // [16,22536,80]
    const float* boxes   = (const float*)d_in[2];   // [16,32,4]
    const int*   labels  = (const int*)d_in[3];     // [16,32]
    const float* priors  = (const float*)d_in[4];   // [22536,4]
    float* out = (float*)d_out;

    k_init<<<2, 256>>>();

    dim3 mg((PP + 255) / 256, BB);
    k_match<<<mg, 256>>>(boxes, priors);

    k_force<<<1, 32>>>();

    int nblk = (BB * PP + 255) / 256;   // 1409
    k_loss<<<nblk, 256>>>(plocs, pscores, boxes, labels, priors);

    k_final<<<1, 256>>>(out, nblk);
}

// round 2
// speedup vs baseline: 1.1636x; 1.1636x over previous
#include <cuda_runtime.h>
#include <cstdint>
#include <cstddef>

#define BB   16
#define PP   22536
#define NOBJ 32
#define NCLS 80
#define NE4  (BB * PP * (NCLS / 4))          // 7,211,520 float4 elements
#define LOSS_ITER 4
#define LOSS_TPB  256
#define LOSS_BLOCKS ((NE4 + LOSS_TPB * LOSS_ITER - 1) / (LOSS_TPB * LOSS_ITER))  // 7043

// ---------------- persistent device scratch (no allocs allowed) ---------------
__device__ unsigned long long g_obj_key[BB * NOBJ];   // per-(img,obj): (iou_bits<<32)|~prior
__device__ float g_best_ov[BB * PP];                  // per-prior best overlap
__device__ int   g_best_obj[BB * PP];                 // per-prior best object idx
__device__ float g_conf_part[8192];
__device__ float g_loc_part[8192];
__device__ int   g_npos_part[8192];

// -------- IoU: textually identical arithmetic in both matching kernels --------
__device__ __forceinline__ float iou_fn(float px1, float py1, float px2, float py2,
                                        float parea, float4 bx) {
    float ltx = fmaxf(px1, bx.x), lty = fmaxf(py1, bx.y);
    float rbx = fminf(px2, bx.z), rby = fminf(py2, bx.w);
    float iw = fmaxf(rbx - ltx, 0.0f), ih = fmaxf(rby - lty, 0.0f);
    float inter = iw * ih;
    float ab = (bx.z - bx.x) * (bx.w - bx.y);
    return __fdividef(inter, parea + ab - inter);
}

// ---------------- per-prior argmax over 32 objects (no shuffles) --------------
__global__ void __launch_bounds__(256)
k_prior(const float* __restrict__ boxes, const float* __restrict__ priors) {
    int b   = blockIdx.y;
    int pr  = blockIdx.x * blockDim.x + threadIdx.x;

    __shared__ float4 sbox[NOBJ];
    if (threadIdx.x < NOBJ)
        sbox[threadIdx.x] = ((const float4*)boxes)[b * NOBJ + threadIdx.x];
    __syncthreads();

    if (pr >= PP) return;

    float4 pc = ((const float4*)priors)[pr];
    float hx = 0.5f * pc.z, hy = 0.5f * pc.w;
    float px1 = pc.x - hx, py1 = pc.y - hy;
    float px2 = pc.x + hx, py2 = pc.y + hy;
    float parea = (px2 - px1) * (py2 - py1);

    float best = -1.0f;
    int   besto = 0;
    #pragma unroll 8
    for (int o = 0; o < NOBJ; o++) {
        float iou = iou_fn(px1, py1, px2, py2, parea, sbox[o]);
        if (iou > best) { best = iou; besto = o; }   // strict > => first-max
    }
    g_best_ov[b * PP + pr]  = best;
    g_best_obj[b * PP + pr] = besto;
}

// -------- per-object argmax over priors: one block per (obj, img) -------------
__global__ void __launch_bounds__(256)
k_obj(const float* __restrict__ boxes, const float* __restrict__ priors) {
    int o = blockIdx.x;
    int b = blockIdx.y;
    float4 bx = ((const float4*)boxes)[b * NOBJ + o];

    unsigned long long key = 0ull;
    for (int pr = threadIdx.x; pr < PP; pr += 256) {
        float4 pc = ((const float4*)priors)[pr];
        float hx = 0.5f * pc.z, hy = 0.5f * pc.w;
        float px1 = pc.x - hx, py1 = pc.y - hy;
        float px2 = pc.x + hx, py2 = pc.y + hy;
        float parea = (px2 - px1) * (py2 - py1);
        float iou = iou_fn(px1, py1, px2, py2, parea, bx);
        unsigned long long k = (((unsigned long long)__float_as_uint(iou)) << 32)
                             | (unsigned long long)(0xFFFFFFFFu - (unsigned)pr);
        if (k > key) key = k;
    }
    // warp reduce
    #pragma unroll
    for (int s = 16; s > 0; s >>= 1) {
        unsigned long long other = __shfl_xor_sync(0xFFFFFFFFu, key, s);
        if (other > key) key = other;
    }
    __shared__ unsigned long long swk[8];
    int lane = threadIdx.x & 31, wid = threadIdx.x >> 5;
    if (lane == 0) swk[wid] = key;
    __syncthreads();
    if (threadIdx.x == 0) {
        #pragma unroll
        for (int w = 1; w < 8; w++)
            if (swk[w] > key) key = swk[w];
        g_obj_key[b * NOBJ + o] = key;
    }
}

// ------------- force best prior per object (sequential, replicates jax scatter) ----
__global__ void k_force() {
    int b = threadIdx.x;
    if (b >= BB) return;
    int cnt = 0;
    for (int j = 0; j < NOBJ; j++) {
        unsigned long long key = g_obj_key[b * NOBJ + j];
        float ov = __uint_as_float((unsigned)(key >> 32));
        if (ov > 0.0f) {                     // valid object
            int pr = (int)(0xFFFFFFFFu - (unsigned)(key & 0xFFFFFFFFull));
            g_best_ov[b * PP + pr]  = 1.0f;
            g_best_obj[b * PP + pr] = cnt;   // filtered-list index (cumsum(valid)-1)
            cnt++;
        }
    }
}

// ---------------- focal helpers -----------------------------------------------
// g(x) = sigmoid(x)^2 * softplus(x)
__device__ __forceinline__ float gfun(float x) {
    float ax = fabsf(x);
    float a  = __expf(-ax);        // MUFU.EX2
    float u  = 1.0f + a;
    float L  = __logf(u);          // MUFU.LG2 : log1p(a)
    float r;
    asm("rcp.approx.f32 %0, %1;" : "=f"(r) : "f"(u));   // MUFU.RCP
    float s  = (x >= 0.0f) ? r : a * r;
    float sp = fmaxf(x, 0.0f) + L;
    return s * s * sp;
}

__device__ __forceinline__ float sl1(float d) {
    float ad = fabsf(d);
    return (ad < 1.0f) ? 0.5f * d * d : ad - 0.5f;
}

// ---------------- fused flat focal + smooth-L1 loss ----------------------------
// One thread per float4 of the flat [B*P, 80] score matrix -> fully coalesced.
__global__ void __launch_bounds__(LOSS_TPB)
k_loss(const float* __restrict__ plocs, const float* __restrict__ pscores,
       const float* __restrict__ boxes, const int* __restrict__ labels,
       const float* __restrict__ priors) {
    const float4* sc4 = (const float4*)pscores;
    float conf = 0.0f, loc = 0.0f;
    int np = 0;

    int base = blockIdx.x * (LOSS_TPB * LOSS_ITER) + threadIdx.x;
    #pragma unroll
    for (int it = 0; it < LOSS_ITER; it++) {
        int e4 = base + it * LOSS_TPB;
        if (e4 >= NE4) break;
        int row  = e4 / (NCLS / 4);          // /20
        int col4 = e4 - row * (NCLS / 4);
        int b    = row / PP;

        float ov = g_best_ov[row];
        int t = 0;
        int obj = 0;
        if (ov >= 0.4f) {
            if (ov < 0.5f) t = -1;
            else {
                obj = g_best_obj[row];
                t = labels[b * NOBJ + obj];
            }
        }

        if (t >= 0) {
            float4 v = sc4[e4];
            int col = col4 * 4;
            #pragma unroll
            for (int j = 0; j < 4; j++) {
                float x = (j == 0) ? v.x : (j == 1) ? v.y : (j == 2) ? v.z : v.w;
                bool isp = (t > 0) && (col + j == t - 1);
                float w  = isp ? 0.25f : 0.75f;
                float xe = isp ? -x : x;
                conf += w * gfun(xe);
            }
            if (t > 0 && col4 == 0) {
                np = 1;
                int pr = row - b * PP;
                float4 bx  = ((const float4*)boxes)[b * NOBJ + obj];
                float4 pcv = ((const float4*)priors)[pr];
                float cx = 0.5f * (bx.x + bx.z), cy = 0.5f * (bx.y + bx.w);
                float w2 = bx.z - bx.x,          h2 = bx.w - bx.y;
                float g0 = __fdividef(cx - pcv.x, 0.1f * pcv.z);
                float g1 = __fdividef(cy - pcv.y, 0.1f * pcv.w);
                float g2 = 5.0f * __logf(__fdividef(w2, pcv.z));
                float g3 = 5.0f * __logf(__fdividef(h2, pcv.w));
                float4 pl = ((const float4*)plocs)[row];
                loc = sl1(pl.x - g0) + sl1(pl.y - g1) + sl1(pl.z - g2) + sl1(pl.w - g3);
            }
        }
    }

    // block reduction: warp shuffle then smem across warps
    #pragma unroll
    for (int s = 16; s > 0; s >>= 1) {
        conf += __shfl_xor_sync(0xFFFFFFFFu, conf, s);
        loc  += __shfl_xor_sync(0xFFFFFFFFu, loc, s);
        np   += __shfl_xor_sync(0xFFFFFFFFu, np, s);
    }
    __shared__ float swc[8], swl[8];
    __shared__ int   swn[8];
    int lane = threadIdx.x & 31, wid = threadIdx.x >> 5;
    if (lane == 0) { swc[wid] = conf; swl[wid] = loc; swn[wid] = np; }
    __syncthreads();
    if (threadIdx.x == 0) {
        float c = 0.0f, l = 0.0f; int n = 0;
        #pragma unroll
        for (int w = 0; w < 8; w++) { c += swc[w]; l += swl[w]; n += swn[w]; }
        g_conf_part[blockIdx.x] = c;
        g_loc_part[blockIdx.x]  = l;
        g_npos_part[blockIdx.x] = n;
    }
}

// ---------------- final deterministic reduction --------------------------------
__global__ void k_final(float* __restrict__ out, int nblk) {
    __shared__ double sc[256];
    __shared__ double sl[256];
    __shared__ int    sn[256];
    int tid = threadIdx.x;
    double c = 0.0, l = 0.0;
    int n = 0;
    for (int i = tid; i < nblk; i += 256) {
        c += (double)g_conf_part[i];
        l += (double)g_loc_part[i];
        n += g_npos_part[i];
    }
    sc[tid] = c; sl[tid] = l; sn[tid] = n;
    __syncthreads();
    #pragma unroll
    for (int s = 128; s > 0; s >>= 1) {
        if (tid < s) {
            sc[tid] += sc[tid + s];
            sl[tid] += sl[tid + s];
            sn[tid] += sn[tid + s];
        }
        __syncthreads();
    }
    if (tid == 0) {
        double npos = (double)(sn[0] > 1 ? sn[0] : 1);
        out[0] = (float)(sc[0] / npos + sl[0] / (npos * 4.0));
    }
}

// ---------------- launch ---------------------------------------------------------
extern "C" void kernel_launch(void* const* d_in, const int* in_sizes, int n_in,
                              void* d_out, int out_size) {
    const float* plocs   = (const float*)d_in[0];   // [16,22536,4]
    const float* pscores = (const float*)d_in[1];   // [16,22536,80]
    const float* boxes   = (const float*)d_in[2];   // [16,32,4]
    const int*   labels  = (const int*)d_in[3];     // [16,32]
    const float* priors  = (const float*)d_in[4];   // [22536,4]
    float* out = (float*)d_out;

    dim3 pg((PP + 255) / 256, BB);
    k_prior<<<pg, 256>>>(boxes, priors);

    dim3 og(NOBJ, BB);
    k_obj<<<og, 256>>>(boxes, priors);

    k_force<<<1, 32>>>();

    k_loss<<<LOSS_BLOCKS, LOSS_TPB>>>(plocs, pscores, boxes, labels, priors);

    k_final<<<1, 256>>>(out, LOSS_BLOCKS);
}

// round 4
// speedup vs baseline: 1.3167x; 1.1316x over previous
#include <cuda_runtime.h>
#include <cstdint>
#include <cstddef>

#define BB   16
#define PP   22536
#define NOBJ 32
#define NCLS 80
#define NROW (BB * PP)                       // 360,576
#define NE4  (NROW * (NCLS / 4))             // 7,211,520 float4 elements
#define LOSS_TPB  256
#define LOSS_ITER 5
#define LOSS_BLOCKS (NE4 / (LOSS_TPB * LOSS_ITER))   // 5634 exactly
#define TGT_BLOCKS ((NROW + 255) / 256)              // 1409

// ---------------- persistent device scratch (no allocs allowed) ---------------
__device__ unsigned long long g_obj_key[BB * NOBJ];
__device__ float g_best_ov[NROW];
__device__ int   g_best_obj[NROW];
__device__ float g_w[NROW];                  // per-row weight: 1 (use) or 0 (ignore)
__device__ float g_conf_part[8192];          // main all-negative sums (unscaled)
__device__ float g_corr_part[2048];          // positive-column corrections (scaled)
__device__ float g_loc_part[2048];
__device__ int   g_npos_part[2048];

// ---------------- MUFU wrappers ------------------------------------------------
__device__ __forceinline__ float ex2f(float x) {
    float r;
    asm("ex2.approx.f32 %0, %1;" : "=f"(r) : "f"(x));
    return r;
}
__device__ __forceinline__ float lg2f(float x) {
    float r;
    asm("lg2.approx.f32 %0, %1;" : "=f"(r) : "f"(x));
    return r;
}

// -------- IoU: textually identical arithmetic in both matching kernels --------
__device__ __forceinline__ float iou_fn(float px1, float py1, float px2, float py2,
                                        float parea, float4 bx) {
    float ltx = fmaxf(px1, bx.x), lty = fmaxf(py1, bx.y);
    float rbx = fminf(px2, bx.z), rby = fminf(py2, bx.w);
    float iw = fmaxf(rbx - ltx, 0.0f), ih = fmaxf(rby - lty, 0.0f);
    float inter = iw * ih;
    float ab = (bx.z - bx.x) * (bx.w - bx.y);
    return __fdividef(inter, parea + ab - inter);
}

// ---------------- per-prior argmax over 32 objects ----------------------------
__global__ void __launch_bounds__(256)
k_prior(const float* __restrict__ boxes, const float* __restrict__ priors) {
    int b   = blockIdx.y;
    int pr  = blockIdx.x * blockDim.x + threadIdx.x;

    __shared__ float4 sbox[NOBJ];
    if (threadIdx.x < NOBJ)
        sbox[threadIdx.x] = ((const float4*)boxes)[b * NOBJ + threadIdx.x];
    __syncthreads();

    if (pr >= PP) return;

    float4 pc = ((const float4*)priors)[pr];
    float hx = 0.5f * pc.z, hy = 0.5f * pc.w;
    float px1 = pc.x - hx, py1 = pc.y - hy;
    float px2 = pc.x + hx, py2 = pc.y + hy;
    float parea = (px2 - px1) * (py2 - py1);

    float best = -1.0f;
    int   besto = 0;
    #pragma unroll 8
    for (int o = 0; o < NOBJ; o++) {
        float iou = iou_fn(px1, py1, px2, py2, parea, sbox[o]);
        if (iou > best) { best = iou; besto = o; }   // strict > => first-max
    }
    g_best_ov[b * PP + pr]  = best;
    g_best_obj[b * PP + pr] = besto;
}

// -------- per-object argmax over priors: one block per (obj, img) -------------
__global__ void __launch_bounds__(256)
k_obj(const float* __restrict__ boxes, const float* __restrict__ priors) {
    int o = blockIdx.x;
    int b = blockIdx.y;
    float4 bx = ((const float4*)boxes)[b * NOBJ + o];

    unsigned long long key = 0ull;
    for (int pr = threadIdx.x; pr < PP; pr += 256) {
        float4 pc = ((const float4*)priors)[pr];
        float hx = 0.5f * pc.z, hy = 0.5f * pc.w;
        float px1 = pc.x - hx, py1 = pc.y - hy;
        float px2 = pc.x + hx, py2 = pc.y + hy;
        float parea = (px2 - px1) * (py2 - py1);
        float iou = iou_fn(px1, py1, px2, py2, parea, bx);
        unsigned long long k = (((unsigned long long)__float_as_uint(iou)) << 32)
                             | (unsigned long long)(0xFFFFFFFFu - (unsigned)pr);
        if (k > key) key = k;
    }
    #pragma unroll
    for (int s = 16; s > 0; s >>= 1) {
        unsigned long long other = __shfl_xor_sync(0xFFFFFFFFu, key, s);
        if (other > key) key = other;
    }
    __shared__ unsigned long long swk[8];
    int lane = threadIdx.x & 31, wid = threadIdx.x >> 5;
    if (lane == 0) swk[wid] = key;
    __syncthreads();
    if (threadIdx.x == 0) {
        #pragma unroll
        for (int w = 1; w < 8; w++)
            if (swk[w] > key) key = swk[w];
        g_obj_key[b * NOBJ + o] = key;
    }
}

// ------------- force best prior per object (sequential jax scatter) -----------
__global__ void k_force() {
    int b = threadIdx.x;
    if (b >= BB) return;
    int cnt = 0;
    for (int j = 0; j < NOBJ; j++) {
        unsigned long long key = g_obj_key[b * NOBJ + j];
        float ov = __uint_as_float((unsigned)(key >> 32));
        if (ov > 0.0f) {
            int pr = (int)(0xFFFFFFFFu - (unsigned)(key & 0xFFFFFFFFull));
            g_best_ov[b * PP + pr]  = 1.0f;
            g_best_obj[b * PP + pr] = cnt;
            cnt++;
        }
    }
}

// ---------------- log2-domain focal core --------------------------------------
// returns g(x)/ln2 where g(x) = sigmoid(x)^2 * softplus(x)
__device__ __forceinline__ float gfun2(float x) {
    const float L2E = 1.4426950408889634f;
    float y  = x * L2E;
    float A  = ex2f(-fabsf(y));
    float L2 = lg2f(1.0f + A);
    float e  = fmaxf(-y, 0.0f) + L2;          // softplus(-x)/ln2
    float q  = fmaxf( y, 0.0f) + L2;          // softplus(x)/ln2
    float G  = ex2f(-2.0f * e);               // sigmoid(x)^2
    return G * q;
}

__device__ __forceinline__ float sl1(float d) {
    float ad = fabsf(d);
    return (ad < 1.0f) ? 0.5f * d * d : ad - 0.5f;
}

// -------- per-row targets + sparse positive corrections + loc loss ------------
__global__ void __launch_bounds__(256)
k_tgt(const float* __restrict__ plocs, const float* __restrict__ pscores,
      const float* __restrict__ boxes, const int* __restrict__ labels,
      const float* __restrict__ priors) {
    const float LN2 = 0.6931471805599453f;
    int row = blockIdx.x * blockDim.x + threadIdx.x;
    float corr = 0.0f, loc = 0.0f;
    int np = 0;

    if (row < NROW) {
        int b = row / PP;
        float ov = g_best_ov[row];
        int t = 0;
        int obj = 0;
        if (ov >= 0.4f) {
            if (ov < 0.5f) t = -1;
            else {
                obj = g_best_obj[row];
                t = labels[b * NOBJ + obj];
            }
        }
        g_w[row] = (t >= 0) ? 1.0f : 0.0f;

        if (t > 0) {
            np = 1;
            int pr = row - b * PP;
            float xk = pscores[(size_t)row * NCLS + (t - 1)];
            corr = LN2 * (0.25f * gfun2(-xk) - 0.75f * gfun2(xk));

            float4 bx  = ((const float4*)boxes)[b * NOBJ + obj];
            float4 pcv = ((const float4*)priors)[pr];
            float cx = 0.5f * (bx.x + bx.z), cy = 0.5f * (bx.y + bx.w);
            float w2 = bx.z - bx.x,          h2 = bx.w - bx.y;
            float g0 = __fdividef(cx - pcv.x, 0.1f * pcv.z);
            float g1 = __fdividef(cy - pcv.y, 0.1f * pcv.w);
            float g2 = 5.0f * __logf(__fdividef(w2, pcv.z));
            float g3 = 5.0f * __logf(__fdividef(h2, pcv.w));
            float4 pl = ((const float4*)plocs)[row];
            loc = sl1(pl.x - g0) + sl1(pl.y - g1) + sl1(pl.z - g2) + sl1(pl.w - g3);
        }
    }

    #pragma unroll
    for (int s = 16; s > 0; s >>= 1) {
        corr += __shfl_xor_sync(0xFFFFFFFFu, corr, s);
        loc  += __shfl_xor_sync(0xFFFFFFFFu, loc, s);
        np   += __shfl_xor_sync(0xFFFFFFFFu, np, s);
    }
    __shared__ float swc[8], swl[8];
    __shared__ int   swn[8];
    int lane = threadIdx.x & 31, wid = threadIdx.x >> 5;
    if (lane == 0) { swc[wid] = corr; swl[wid] = loc; swn[wid] = np; }
    __syncthreads();
    if (threadIdx.x == 0) {
        float c = 0.0f, l = 0.0f; int n = 0;
        #pragma unroll
        for (int w = 0; w < 8; w++) { c += swc[w]; l += swl[w]; n += swn[w]; }
        g_corr_part[blockIdx.x] = c;
        g_loc_part[blockIdx.x]  = l;
        g_npos_part[blockIdx.x] = n;
    }
}

// ---------------- big streaming focal kernel (branchless) ---------------------
__global__ void __launch_bounds__(LOSS_TPB)
k_loss(const float* __restrict__ pscores) {
    const float4* sc4 = (const float4*)pscores;
    float conf = 0.0f;

    int base = blockIdx.x * (LOSS_TPB * LOSS_ITER) + threadIdx.x;
    #pragma unroll
    for (int it = 0; it < LOSS_ITER; it++) {
        int e4  = base + it * LOSS_TPB;        // always < NE4 (exact grid)
        int row = e4 / (NCLS / 4);             // const-div by 20
        float w = __ldg(&g_w[row]);
        float4 v = sc4[e4];
        float s4 = gfun2(v.x) + gfun2(v.y) + gfun2(v.z) + gfun2(v.w);
        conf = fmaf(w, s4, conf);
    }

    #pragma unroll
    for (int s = 16; s > 0; s >>= 1)
        conf += __shfl_xor_sync(0xFFFFFFFFu, conf, s);
    __shared__ float swc[8];
    int lane = threadIdx.x & 31, wid = threadIdx.x >> 5;
    if (lane == 0) swc[wid] = conf;
    __syncthreads();
    if (threadIdx.x == 0) {
        float c = 0.0f;
        #pragma unroll
        for (int w = 0; w < 8; w++) c += swc[w];
        g_conf_part[blockIdx.x] = c;
    }
}

// ---------------- final deterministic reduction --------------------------------
__global__ void k_final(float* __restrict__ out) {
    __shared__ double sc[256];
    __shared__ double sl[256];
    __shared__ int    sn[256];
    int tid = threadIdx.x;
    double c = 0.0, l = 0.0;
    int n = 0;
    for (int i = tid; i < LOSS_BLOCKS; i += 256)
        c += (double)g_conf_part[i];
    double corr = 0.0;
    for (int i = tid; i < TGT_BLOCKS; i += 256) {
        corr += (double)g_corr_part[i];
        l    += (double)g_loc_part[i];
        n    += g_npos_part[i];
    }
    const double SCALE = 0.75 * 0.6931471805599453;   // 0.75 * ln2
    sc[tid] = c * SCALE + corr; sl[tid] = l; sn[tid] = n;
    __syncthreads();
    #pragma unroll
    for (int s = 128; s > 0; s >>= 1) {
        if (tid < s) {
            sc[tid] += sc[tid + s];
            sl[tid] += sl[tid + s];
            sn[tid] += sn[tid + s];
        }
        __syncthreads();
    }
    if (tid == 0) {
        double npos = (double)(sn[0] > 1 ? sn[0] : 1);
        out[0] = (float)(sc[0] / npos + sl[0] / (npos * 4.0));
    }
}

// ---------------- launch ---------------------------------------------------------
extern "C" void kernel_launch(void* const* d_in, const int* in_sizes, int n_in,
                              void* d_out, int out_size) {
    const float* plocs   = (const float*)d_in[0];
    const float* pscores = (const float*)d_in[1];
    const float* boxes   = (const float*)d_in[2];
    const int*   labels  = (const int*)d_in[3];
    const float* priors  = (const float*)d_in[4];
    float* out = (float*)d_out;

    dim3 pg((PP + 255) / 256, BB);
    k_prior<<<pg, 256>>>(boxes, priors);

    dim3 og(NOBJ, BB);
    k_obj<<<og, 256>>>(boxes, priors);

    k_force<<<1, 32>>>();

    k_tgt<<<TGT_BLOCKS, 256>>>(plocs, pscores, boxes, labels, priors);

    k_loss<<<LOSS_BLOCKS, LOSS_TPB>>>(pscores);

    k_final<<<1, 256>>>(out);
}